// round 6
// baseline (speedup 1.0000x reference)
#include <cuda_runtime.h>
#include <cstdint>
#include <math.h>

#define TOKENS 32768
#define NEXP   64
#define KDIM   2048
#define KC     32              // floats per K-chunk (2 k16 steps)
#define NCH    (KDIM / KC)     // 64 chunks
#define TILE_M 128
#define TPB    256
#define NKB16  (KDIM / 16)     // 128 k16 blocks

// W pre-split, fragment-ready bf16: [kb16(128)][nf(8)][lane(32)] = {bh0,bh1,bm0,bm1}
__device__ uint4 g_wperm[NKB16 * 8 * 32];   // 512 KB

static __device__ __forceinline__ uint32_t bfpack(float hi, float lo) {
    uint32_t d;
    asm("cvt.rn.bf16x2.f32 %0, %1, %2;" : "=r"(d) : "f"(hi), "f"(lo));
    return d;
}
static __device__ __forceinline__ float bflo(uint32_t p) { return __uint_as_float(p << 16); }
static __device__ __forceinline__ float bfhi(uint32_t p) { return __uint_as_float(p & 0xFFFF0000u); }

static __device__ __forceinline__ void split_pair(float a, float b, uint32_t& h, uint32_t& m) {
    h = bfpack(b, a);                       // lo = a, hi = b
    m = bfpack(b - bfhi(h), a - bflo(h));
}

static __device__ __forceinline__ void mma16(float* d, const uint32_t* a,
                                             uint32_t b0, uint32_t b1) {
    asm volatile(
        "mma.sync.aligned.m16n8k16.row.col.f32.bf16.bf16.f32 "
        "{%0,%1,%2,%3}, {%4,%5,%6,%7}, {%8,%9}, {%0,%1,%2,%3};"
        : "+f"(d[0]), "+f"(d[1]), "+f"(d[2]), "+f"(d[3])
        : "r"(a[0]), "r"(a[1]), "r"(a[2]), "r"(a[3]), "r"(b0), "r"(b1));
}
static __device__ __forceinline__ void merge2(float& v1, int& i1, float& v2, int& i2, int off) {
    float ov1 = __shfl_xor_sync(0xffffffffu, v1, off);
    int   oi1 = __shfl_xor_sync(0xffffffffu, i1, off);
    float ov2 = __shfl_xor_sync(0xffffffffu, v2, off);
    int   oi2 = __shfl_xor_sync(0xffffffffu, i2, off);
    bool mine = (v1 > ov1) || (v1 == ov1 && i1 < oi1);
    float l1v = mine ? ov1 : v1;  int l1i = mine ? oi1 : i1;
    float s2v = mine ? v2  : ov2; int s2i = mine ? i2  : oi2;
    v1 = mine ? v1 : ov1;  i1 = mine ? i1 : oi1;
    bool sec = (s2v > l1v) || (s2v == l1v && s2i < l1i);
    v2 = sec ? s2v : l1v;  i2 = sec ? s2i : l1i;
}

// ---- prep: split W into bf16 fragment-ready layout (once per launch) ----
extern "C" __global__ void __launch_bounds__(256)
prep_w(const float* __restrict__ W)
{
    int idx  = blockIdx.x * 256 + threadIdx.x;  // 0..32767
    int lane = idx & 31;
    int nf   = (idx >> 5) & 7;
    int kb   = idx >> 8;                        // k16 block 0..127
    int g = lane >> 2, t = lane & 3;
    const float* wr = W + (size_t)(nf * 8 + g) * KDIM + kb * 16;
    uint4 r;
    split_pair(wr[2 * t],     wr[2 * t + 1], r.x, r.z);   // b0 (k = 2t, 2t+1)
    split_pair(wr[2 * t + 8], wr[2 * t + 9], r.y, r.w);   // b1 (k = 2t+8, 2t+9)
    g_wperm[idx] = r;
}

// SMEM per stage (uint4 units): aH[512] | aM[512] | B[512]  -> 1536 uint4 = 24KB
#define STAGE_U4  1536
#define SMEM_BYTES (2 * STAGE_U4 * 16)   // 49152

extern "C" __global__ void __launch_bounds__(TPB, 2)
router_hom(const float* __restrict__ X, float* __restrict__ out)
{
    extern __shared__ uint4 sm4[];
    const int tid  = threadIdx.x;
    const int wid  = tid >> 5;
    const int lane = tid & 31;
    const int g    = lane >> 2;
    const int t    = lane & 3;
    const int wg   = wid >> 1;    // row group: rows [wg*32, wg*32+32)
    const int ng   = wid & 1;     // expert half: cols [ng*32, ng*32+32)
    const int blockM = blockIdx.x * TILE_M;

    // staging regs: every thread loads 2 A-slots (16 floats) + 2 B-slots, x2 buffers
    float4 xa[2][2], xb[2][2];
    uint4  bb[2][2];

    #define PLOAD(c, rb)                                                        \
        {                                                                       \
            _Pragma("unroll")                                                   \
            for (int j = 0; j < 2; j++) {                                       \
                int s_idx = tid + 256 * j;        /* 0..511 */                  \
                int row = s_idx >> 2, q2 = s_idx & 3;                           \
                const float* src = X + (size_t)(blockM + row) * KDIM            \
                                     + (size_t)(c) * KC + q2 * 8;               \
                xa[rb][j] = reinterpret_cast<const float4*>(src)[0];            \
                xb[rb][j] = reinterpret_cast<const float4*>(src)[1];            \
                bb[rb][j] = g_wperm[(c) * 512 + s_idx];                         \
            }                                                                   \
        }
    #define PSTORE(c, rb)                                                       \
        {                                                                       \
            uint4* aH = sm4 + ((c) & 1) * STAGE_U4;                             \
            uint4* aM = aH + 512;                                               \
            uint4* sB = aH + 1024;                                              \
            _Pragma("unroll")                                                   \
            for (int j = 0; j < 2; j++) {                                       \
                int s_idx = tid + 256 * j;                                      \
                int row = s_idx >> 2, q2 = s_idx & 3;                           \
                uint4 H, M;                                                     \
                split_pair(xa[rb][j].x, xa[rb][j].y, H.x, M.x);                 \
                split_pair(xa[rb][j].z, xa[rb][j].w, H.y, M.y);                 \
                split_pair(xb[rb][j].x, xb[rb][j].y, H.z, M.z);                 \
                split_pair(xb[rb][j].z, xb[rb][j].w, H.w, M.w);                 \
                int a_idx = q2 * 128 + (row ^ (2 * q2));                        \
                aH[a_idx]  = H;                                                 \
                aM[a_idx]  = M;                                                 \
                sB[s_idx]  = bb[rb][j];                                         \
            }                                                                   \
        }

    float acc[2][4][4];
    #pragma unroll
    for (int mf = 0; mf < 2; mf++)
        #pragma unroll
        for (int nf = 0; nf < 4; nf++)
            #pragma unroll
            for (int u = 0; u < 4; u++) acc[mf][nf][u] = 0.0f;

    // prologue: stage chunk 0, prefetch chunk 1
    PLOAD(0, 0);
    PSTORE(0, 0);
    PLOAD(1, 1);
    __syncthreads();

    for (int c = 0; c < NCH; c++) {
        // stage chunk c+1 into the other buffer; prefetch chunk c+2
        if (c + 1 < NCH) PSTORE(c + 1, (c + 1) & 1);
        if (c + 2 < NCH) PLOAD(c + 2, c & 1);

        // MMA on chunk c
        const int s = c & 1;
        const uint32_t* aH = reinterpret_cast<const uint32_t*>(sm4 + s * STAGE_U4);
        const uint32_t* aM = aH + 2048;
        const uint4*    sB = sm4 + s * STAGE_U4 + 1024;

        #pragma unroll
        for (int kb = 0; kb < 2; kb++) {
            uint32_t ah[2][4], am[2][4];
            #pragma unroll
            for (int mf = 0; mf < 2; mf++) {
                const int R0 = wg * 32 + mf * 16 + g;
                const int i0 = ((2 * kb) * 128 + (R0 ^ (4 * kb))) * 4 + t;
                const int i2 = ((2 * kb + 1) * 128 + (R0 ^ (4 * kb + 2))) * 4 + t;
                ah[mf][0] = aH[i0];       ah[mf][1] = aH[i0 + 32];
                ah[mf][2] = aH[i2];       ah[mf][3] = aH[i2 + 32];
                am[mf][0] = aM[i0];       am[mf][1] = aM[i0 + 32];
                am[mf][2] = aM[i2];       am[mf][3] = aM[i2 + 32];
            }
            #pragma unroll
            for (int nf = 0; nf < 4; nf++) {
                uint4 b = sB[(kb * 8 + ng * 4 + nf) * 32 + lane];
                #pragma unroll
                for (int mf = 0; mf < 2; mf++) {
                    mma16(acc[mf][nf], ah[mf], b.x, b.y);   // Ah*Bh
                    mma16(acc[mf][nf], ah[mf], b.z, b.w);   // Ah*Bm
                    mma16(acc[mf][nf], am[mf], b.x, b.y);   // Am*Bh
                }
            }
        }
        __syncthreads();
    }

    // ---------------- epilogue ----------------
    float* outIdx = out;
    float* outWgt = out + TOKENS * 2;
    float* outLog = out + TOKENS * 4;
    float4* cand = reinterpret_cast<float4*>(sm4);   // [128] per-row ng=1 candidates

    float hv1[4], hv2[4];   // per (mf,h) half-top2
    int   hi1[4], hi2[4];

    #pragma unroll
    for (int mf = 0; mf < 2; mf++) {
        #pragma unroll
        for (int h = 0; h < 2; h++) {
            const int row = wg * 32 + mf * 16 + h * 8 + g;
            const int tok = blockM + row;

            float v1 = -INFINITY, v2 = -INFINITY;
            int   i1 = 0, i2 = 0;
            #pragma unroll
            for (int nf = 0; nf < 4; nf++) {
                #pragma unroll
                for (int u = 0; u < 2; u++) {
                    float v  = acc[mf][nf][2 * h + u];
                    int   id = ng * 32 + nf * 8 + 2 * t + u;
                    if (v > v1)      { v2 = v1; i2 = i1; v1 = v; i1 = id; }
                    else if (v > v2) { v2 = v;  i2 = id; }
                }
            }
            merge2(v1, i1, v2, i2, 1);
            merge2(v1, i1, v2, i2, 2);
            hv1[mf * 2 + h] = v1; hi1[mf * 2 + h] = i1;
            hv2[mf * 2 + h] = v2; hi2[mf * 2 + h] = i2;

            // logits: this warp owns cols ng*32 + nf*8 + {2t, 2t+1}
            float* lr = outLog + (size_t)tok * NEXP + ng * 32;
            #pragma unroll
            for (int nf = 0; nf < 4; nf++) {
                float2 o = make_float2(acc[mf][nf][2 * h], acc[mf][nf][2 * h + 1]);
                *reinterpret_cast<float2*>(lr + nf * 8 + 2 * t) = o;
            }
        }
    }

    // ng=1 publishes per-row candidates
    if (ng == 1 && t == 0) {
        #pragma unroll
        for (int q = 0; q < 4; q++) {
            int mf = q >> 1, h = q & 1;
            int row = wg * 32 + mf * 16 + h * 8 + g;
            cand[row] = make_float4(hv1[q], __int_as_float(hi1[q]),
                                    hv2[q], __int_as_float(hi2[q]));
        }
    }
    __syncthreads();

    // ng=0 merges halves (ng0 ids < ng1 ids -> ties prefer ng0) and writes
    if (ng == 0 && t == 0) {
        #pragma unroll
        for (int q = 0; q < 4; q++) {
            int mf = q >> 1, h = q & 1;
            int row = wg * 32 + mf * 16 + h * 8 + g;
            int tok = blockM + row;
            float4 cb = cand[row];
            float av1 = hv1[q], av2 = hv2[q], bv1 = cb.x, bv2 = cb.z;
            int   ai1 = hi1[q], ai2 = hi2[q], bi1 = __float_as_int(cb.y),
                  bi2 = __float_as_int(cb.w);

            bool btop = (bv1 > av1);
            float f1 = btop ? bv1 : av1;  int j1 = btop ? bi1 : ai1;
            float sa = btop ? av1 : av2;  int ja = btop ? ai1 : ai2;
            float sb = btop ? bv2 : bv1;  int jb = btop ? bi2 : bi1;
            bool aw = (sa >= sb);
            float f2 = aw ? sa : sb;      int j2 = aw ? ja : jb;

            float e2  = expf(f2 - f1);          // f1 >= f2 -> stable
            float inv = 1.0f / (1.0f + e2);
            outIdx[tok * 2]     = (float)j1;
            outIdx[tok * 2 + 1] = (float)j2;
            outWgt[tok * 2]     = inv;
            outWgt[tok * 2 + 1] = e2 * inv;
        }
    }
}

extern "C" void kernel_launch(void* const* d_in, const int* in_sizes, int n_in,
                              void* d_out, int out_size)
{
    const float* X = (const float*)d_in[0];   // [32768, 2048] fp32
    const float* W = (const float*)d_in[1];   // [64, 2048] fp32
    float* out = (float*)d_out;

    prep_w<<<128, 256>>>(W);

    cudaFuncSetAttribute(router_hom,
                         cudaFuncAttributeMaxDynamicSharedMemorySize, SMEM_BYTES);
    router_hom<<<TOKENS / TILE_M, TPB, SMEM_BYTES>>>(X, out);
}

// round 7
// speedup vs baseline: 1.5765x; 1.5765x over previous
#include <cuda_runtime.h>
#include <cstdint>
#include <math.h>

#define TOKENS 32768
#define NEXP   64
#define KDIM   2048
#define KC     64              // floats per K-chunk (4 k16 steps)
#define NCH    (KDIM / KC)     // 32 chunks
#define TILE_M 128
#define TPB    256
#define NKB16  (KDIM / 16)     // 128 k16 blocks

// W pre-split, fragment-ready bf16: [kb16(128)][nf(8)][lane(32)] = {bh0,bh1,bm0,bm1}
__device__ uint4 g_wperm[NKB16 * 8 * 32];   // 512 KB

static __device__ __forceinline__ uint32_t bfpack(float hi, float lo) {
    uint32_t d;
    asm("cvt.rn.bf16x2.f32 %0, %1, %2;" : "=r"(d) : "f"(hi), "f"(lo));
    return d;
}
static __device__ __forceinline__ float bflo(uint32_t p) { return __uint_as_float(p << 16); }
static __device__ __forceinline__ float bfhi(uint32_t p) { return __uint_as_float(p & 0xFFFF0000u); }

static __device__ __forceinline__ void split_pair(float a, float b, uint32_t& h, uint32_t& m) {
    h = bfpack(b, a);                       // lo = a, hi = b
    m = bfpack(b - bfhi(h), a - bflo(h));
}

static __device__ __forceinline__ void mma16(float* d, const uint32_t* a,
                                             uint32_t b0, uint32_t b1) {
    asm volatile(
        "mma.sync.aligned.m16n8k16.row.col.f32.bf16.bf16.f32 "
        "{%0,%1,%2,%3}, {%4,%5,%6,%7}, {%8,%9}, {%0,%1,%2,%3};"
        : "+f"(d[0]), "+f"(d[1]), "+f"(d[2]), "+f"(d[3])
        : "r"(a[0]), "r"(a[1]), "r"(a[2]), "r"(a[3]), "r"(b0), "r"(b1));
}
static __device__ __forceinline__ void merge2(float& v1, int& i1, float& v2, int& i2, int off) {
    float ov1 = __shfl_xor_sync(0xffffffffu, v1, off);
    int   oi1 = __shfl_xor_sync(0xffffffffu, i1, off);
    float ov2 = __shfl_xor_sync(0xffffffffu, v2, off);
    int   oi2 = __shfl_xor_sync(0xffffffffu, i2, off);
    bool mine = (v1 > ov1) || (v1 == ov1 && i1 < oi1);
    float l1v = mine ? ov1 : v1;  int l1i = mine ? oi1 : i1;
    float s2v = mine ? v2  : ov2; int s2i = mine ? i2  : oi2;
    v1 = mine ? v1 : ov1;  i1 = mine ? i1 : oi1;
    bool sec = (s2v > l1v) || (s2v == l1v && s2i < l1i);
    v2 = sec ? s2v : l1v;  i2 = sec ? s2i : l1i;
}

static __device__ __forceinline__ uint32_t s2u(const void* p) {
    uint32_t a;
    asm("{ .reg .u64 t; cvta.to.shared.u64 t, %1; cvt.u32.u64 %0, t; }" : "=r"(a) : "l"(p));
    return a;
}
static __device__ __forceinline__ void cp16(uint32_t dst, const void* src) {
    asm volatile("cp.async.ca.shared.global [%0], [%1], 16;"
                 :: "r"(dst), "l"(src) : "memory");
}

// ---- prep: split W into bf16 fragment-ready layout (once per launch) ----
extern "C" __global__ void __launch_bounds__(256)
prep_w(const float* __restrict__ W)
{
    int idx  = blockIdx.x * 256 + threadIdx.x;  // 0..32767
    int lane = idx & 31;
    int nf   = (idx >> 5) & 7;
    int kb   = idx >> 8;                        // k16 block 0..127
    int g = lane >> 2, t = lane & 3;
    const float* wr = W + (size_t)(nf * 8 + g) * KDIM + kb * 16;
    uint4 r;
    split_pair(wr[2 * t],     wr[2 * t + 1], r.x, r.z);   // b0 (k = 2t, 2t+1)
    split_pair(wr[2 * t + 8], wr[2 * t + 9], r.y, r.w);   // b1 (k = 2t+8, 2t+9)
    g_wperm[idx] = r;
}

// SMEM per stage (uint4 units): aH[1024] | aM[1024] | B[1024]  -> 3072 uint4 = 48KB
#define STAGE_U4  3072
#define SMEM_BYTES (2 * STAGE_U4 * 16)   // 98304

extern "C" __global__ void __launch_bounds__(TPB, 2)
router_bf16(const float* __restrict__ X, float* __restrict__ out)
{
    extern __shared__ uint4 sm4[];
    const int tid  = threadIdx.x;
    const int wid  = tid >> 5;
    const int lane = tid & 31;
    const int g    = lane >> 2;
    const int t    = lane & 3;
    const int blockM = blockIdx.x * TILE_M;

    if (wid >= 4) {
        // ------------- producers: warps 4..7 -------------
        const int p = tid - 128;   // 0..127
        float4 xa[8], xb[8];       // one chunk of A: 64 floats

        // load A chunk c into regs (16 x LDG.128)
        #define PLOAD(c)                                                        \
            {                                                                   \
                _Pragma("unroll")                                               \
                for (int j = 0; j < 8; j++) {                                   \
                    int s_idx = p + 128 * j;          /* 0..1023 */             \
                    int row = s_idx >> 3, q2 = s_idx & 7;                       \
                    const float* src = X + (size_t)(blockM + row) * KDIM        \
                                         + (size_t)(c) * KC + q2 * 8;           \
                    xa[j] = reinterpret_cast<const float4*>(src)[0];            \
                    xb[j] = reinterpret_cast<const float4*>(src)[1];            \
                }                                                               \
            }
        // convert + store A chunk c into stage (c&1)
        #define PSTORE(c)                                                       \
            {                                                                   \
                uint4* aH = sm4 + ((c) & 1) * STAGE_U4;                         \
                uint4* aM = aH + 1024;                                          \
                _Pragma("unroll")                                               \
                for (int j = 0; j < 8; j++) {                                   \
                    int s_idx = p + 128 * j;                                    \
                    int row = s_idx >> 3, q2 = s_idx & 7;                       \
                    uint4 H, M;                                                 \
                    split_pair(xa[j].x, xa[j].y, H.x, M.x);                     \
                    split_pair(xa[j].z, xa[j].w, H.y, M.y);                     \
                    split_pair(xb[j].x, xb[j].y, H.z, M.z);                     \
                    split_pair(xb[j].z, xb[j].w, H.w, M.w);                     \
                    int a_idx = q2 * 128 + (row ^ q2);                          \
                    aH[a_idx] = H;                                              \
                    aM[a_idx] = M;                                              \
                }                                                               \
            }
        // async-copy B chunk c into stage (c&1)
        #define PCOPYB(c)                                                       \
            {                                                                   \
                uint32_t sB = s2u(sm4 + ((c) & 1) * STAGE_U4 + 2048);           \
                _Pragma("unroll")                                               \
                for (int j = 0; j < 8; j++) {                                   \
                    int s_idx = p + 128 * j;                                    \
                    cp16(sB + s_idx * 16, g_wperm + (c) * 1024 + s_idx);        \
                }                                                               \
                asm volatile("cp.async.commit_group;" ::: "memory");            \
            }
        #define PWAIT() asm volatile("cp.async.wait_group 0;" ::: "memory")

        // prologue: stage chunk 0, prefetch chunk 1's A
        PLOAD(0);
        PCOPYB(0);
        PSTORE(0);
        PLOAD(1);
        PWAIT();
        __syncthreads();

        for (int c = 0; c < NCH; c++) {
            if (c + 1 < NCH) {
                PCOPYB(c + 1);
                PSTORE(c + 1);
                if (c + 2 < NCH) PLOAD(c + 2);
                PWAIT();
            }
            __syncthreads();
        }
        return;
    }

    // ------------- consumers: warps 0..3, tile m32 x n64 -------------
    float acc[2][8][4];
    #pragma unroll
    for (int mf = 0; mf < 2; mf++)
        #pragma unroll
        for (int nf = 0; nf < 8; nf++)
            #pragma unroll
            for (int u = 0; u < 4; u++) acc[mf][nf][u] = 0.0f;

    const int wbase = wid * 32;
    __syncthreads();   // match producer prologue

    for (int c = 0; c < NCH; c++) {
        const int s = c & 1;
        const uint32_t* aH = reinterpret_cast<const uint32_t*>(sm4 + s * STAGE_U4);
        const uint32_t* aM = aH + 4096;
        const uint4*    sB = sm4 + s * STAGE_U4 + 2048;

        #pragma unroll
        for (int kb = 0; kb < 4; kb++) {
            const int q0 = 2 * kb, q1 = 2 * kb + 1;
            uint32_t ah[2][4], am[2][4];
            #pragma unroll
            for (int mf = 0; mf < 2; mf++) {
                const int R0 = wbase + mf * 16 + g;
                const int i0 = (q0 * 128 + (R0 ^ q0)) * 4 + t;
                const int i2 = (q1 * 128 + (R0 ^ q1)) * 4 + t;
                ah[mf][0] = aH[i0];       ah[mf][1] = aH[i0 + 32];
                ah[mf][2] = aH[i2];       ah[mf][3] = aH[i2 + 32];
                am[mf][0] = aM[i0];       am[mf][1] = aM[i0 + 32];
                am[mf][2] = aM[i2];       am[mf][3] = aM[i2 + 32];
            }
            #pragma unroll
            for (int nf = 0; nf < 8; nf++) {
                uint4 b = sB[(kb * 8 + nf) * 32 + lane];
                #pragma unroll
                for (int mf = 0; mf < 2; mf++) {
                    mma16(acc[mf][nf], ah[mf], b.x, b.y);   // Ah*Bh
                    mma16(acc[mf][nf], ah[mf], b.z, b.w);   // Ah*Bm
                    mma16(acc[mf][nf], am[mf], b.x, b.y);   // Am*Bh
                }
            }
        }
        __syncthreads();
    }

    // ------------- epilogue: logits + stable top-2 + softmax -------------
    float* outIdx = out;
    float* outWgt = out + TOKENS * 2;
    float* outLog = out + TOKENS * 4;

    #pragma unroll
    for (int mf = 0; mf < 2; mf++) {
        #pragma unroll
        for (int h = 0; h < 2; h++) {
            const int row = wbase + mf * 16 + h * 8 + g;
            const int tok = blockM + row;

            float v1 = -INFINITY, v2 = -INFINITY;
            int   i1 = 0, i2 = 0;
            #pragma unroll
            for (int nf = 0; nf < 8; nf++) {
                #pragma unroll
                for (int u = 0; u < 2; u++) {
                    float v  = acc[mf][nf][2 * h + u];
                    int   id = nf * 8 + 2 * t + u;
                    if (v > v1)      { v2 = v1; i2 = i1; v1 = v; i1 = id; }
                    else if (v > v2) { v2 = v;  i2 = id; }
                }
            }
            merge2(v1, i1, v2, i2, 1);
            merge2(v1, i1, v2, i2, 2);

            float* lr = outLog + (size_t)tok * NEXP;
            #pragma unroll
            for (int nf = 0; nf < 8; nf++) {
                float2 o = make_float2(acc[mf][nf][2 * h], acc[mf][nf][2 * h + 1]);
                *reinterpret_cast<float2*>(lr + nf * 8 + 2 * t) = o;
            }

            if (t == 0) {
                float e2  = expf(v2 - v1);          // v1 >= v2 -> stable
                float inv = 1.0f / (1.0f + e2);
                outIdx[tok * 2]     = (float)i1;
                outIdx[tok * 2 + 1] = (float)i2;
                outWgt[tok * 2]     = inv;
                outWgt[tok * 2 + 1] = e2 * inv;
            }
        }
    }
}

extern "C" void kernel_launch(void* const* d_in, const int* in_sizes, int n_in,
                              void* d_out, int out_size)
{
    const float* X = (const float*)d_in[0];   // [32768, 2048] fp32
    const float* W = (const float*)d_in[1];   // [64, 2048] fp32
    float* out = (float*)d_out;

    prep_w<<<128, 256>>>(W);

    cudaFuncSetAttribute(router_bf16,
                         cudaFuncAttributeMaxDynamicSharedMemorySize, SMEM_BYTES);
    router_bf16<<<TOKENS / TILE_M, TPB, SMEM_BYTES>>>(X, out);
}